// round 2
// baseline (speedup 1.0000x reference)
#include <cuda_runtime.h>
#include <cstdint>

// HashEmbedding:
//   B*L = 819200 tokens, H=2 hashes, E=64 embed, out = [emb(64), pval0, pval1]
// Inputs (metadata order) — JAX without x64: "int64" arrays are really int32:
//   d_in[0] words_as_ids  int32 [819200]
//   d_in[1] hash_table    int32 [1000000, 2]
//   d_in[2] W             f32   [100000, 64]
//   d_in[3] P             f32   [1000000, 2]
// Output: f32 [819200, 66]

static constexpr int NTOK  = 16384 * 50;   // 819200
static constexpr int EMBED = 64;
static constexpr int OUTW  = EMBED + 2;    // 66

__global__ void __launch_bounds__(256)
hash_embedding_kernel(const int*   __restrict__ words,
                      const int2*  __restrict__ hash_table,
                      const float* __restrict__ W,
                      const float2* __restrict__ P2,
                      float*       __restrict__ out)
{
    const int warp = (blockIdx.x * blockDim.x + threadIdx.x) >> 5;
    const int lane = threadIdx.x & 31;
    if (warp >= NTOK) return;

    // All lanes load the same scalar addresses: single-sector, L1 broadcast.
    const int w = __ldg(&words[warp]);

    const int2 h = __ldg(&hash_table[w]);          // 8B aligned (int2)
    const float2 pw = __ldg(&P2[w]);               // per-word weights

    // Gather two W rows: 8 bytes/lane, one coalesced 256B line per row.
    const float2 a = __ldg(reinterpret_cast<const float2*>(W + (size_t)h.x * EMBED) + lane);
    const float2 b = __ldg(reinterpret_cast<const float2*>(W + (size_t)h.y * EMBED) + lane);

    float2 e;
    e.x = fmaf(a.x, pw.x, b.x * pw.y);
    e.y = fmaf(a.y, pw.x, b.y * pw.y);

    float* o = out + (size_t)warp * OUTW;          // 264B stride: 8B aligned
    reinterpret_cast<float2*>(o)[lane] = e;        // cols 0..63

    if (lane == 0) {
        // pvals: P[h0, 0], P[h1, 1]
        const float* Pf = reinterpret_cast<const float*>(P2);
        float2 pv;
        pv.x = __ldg(&Pf[(size_t)h.x * 2 + 0]);
        pv.y = __ldg(&Pf[(size_t)h.y * 2 + 1]);
        *reinterpret_cast<float2*>(o + EMBED) = pv;  // cols 64..65
    }
}

extern "C" void kernel_launch(void* const* d_in, const int* in_sizes, int n_in,
                              void* d_out, int out_size)
{
    const int*    words      = (const int*)d_in[0];
    const int2*   hash_table = (const int2*)d_in[1];
    const float*  W          = (const float*)d_in[2];
    const float2* P          = (const float2*)d_in[3];
    float*        out        = (float*)d_out;

    const int warps_per_block = 256 / 32;                               // 8 tokens/block
    const int blocks = (NTOK + warps_per_block - 1) / warps_per_block;  // 102400
    hash_embedding_kernel<<<blocks, 256>>>(words, hash_table, W, P, out);
}

// round 3
// speedup vs baseline: 1.6377x; 1.6377x over previous
#include <cuda_runtime.h>
#include <cstdint>

// HashEmbedding: B*L=819200 tokens, H=2, E=64, out=[emb(64), pv0, pv1] f32
// d_in: words int32[819200], hash_table int32[1000000,2],
//       W f32[100000,64], P f32[1000000,2]

static constexpr int NTOK  = 16384 * 50;   // 819200
static constexpr int EMBED = 64;
static constexpr int OUTW  = EMBED + 2;    // 66
static constexpr int TPW   = 4;            // tokens per warp

__global__ void __launch_bounds__(256)
hash_embedding_kernel(const int*    __restrict__ words,
                      const int2*   __restrict__ hash_table,
                      const float*  __restrict__ W,
                      const float2* __restrict__ P2,
                      float*        __restrict__ out)
{
    const int warp = (blockIdx.x * blockDim.x + threadIdx.x) >> 5;
    const int lane = threadIdx.x & 31;
    const int base = warp * TPW;
    if (base >= NTOK) return;

    // Stage 1: 4 independent word loads (broadcast; same L2 sector)
    int w[TPW];
#pragma unroll
    for (int t = 0; t < TPW; t++) w[t] = __ldg(&words[base + t]);

    // Stage 2: 8 independent gathers of indices + per-word weights
    int2   h[TPW];
    float2 pw[TPW];
#pragma unroll
    for (int t = 0; t < TPW; t++) h[t]  = __ldg(&hash_table[w[t]]);
#pragma unroll
    for (int t = 0; t < TPW; t++) pw[t] = __ldg(&P2[w[t]]);

    // Stage 3: 8 independent W-row gathers, 8B/lane, coalesced 256B rows;
    // plus pval gathers on lane 0 overlapping the same window.
    float2 a[TPW], b[TPW];
#pragma unroll
    for (int t = 0; t < TPW; t++) {
        a[t] = __ldg(reinterpret_cast<const float2*>(W + (size_t)h[t].x * EMBED) + lane);
        b[t] = __ldg(reinterpret_cast<const float2*>(W + (size_t)h[t].y * EMBED) + lane);
    }

    float2 pv[TPW];
    if (lane == 0) {
        const float* Pf = reinterpret_cast<const float*>(P2);
#pragma unroll
        for (int t = 0; t < TPW; t++) {
            pv[t].x = __ldg(&Pf[(size_t)h[t].x * 2 + 0]);
            pv[t].y = __ldg(&Pf[(size_t)h[t].y * 2 + 1]);
        }
    }

    // Stage 4: compute + store
#pragma unroll
    for (int t = 0; t < TPW; t++) {
        float2 e;
        e.x = fmaf(a[t].x, pw[t].x, b[t].x * pw[t].y);
        e.y = fmaf(a[t].y, pw[t].x, b[t].y * pw[t].y);

        float* o = out + (size_t)(base + t) * OUTW;   // 264B stride, 8B aligned
        reinterpret_cast<float2*>(o)[lane] = e;       // cols 0..63
        if (lane == 0)
            *reinterpret_cast<float2*>(o + EMBED) = pv[t];  // cols 64..65
    }
}

extern "C" void kernel_launch(void* const* d_in, const int* in_sizes, int n_in,
                              void* d_out, int out_size)
{
    const int*    words      = (const int*)d_in[0];
    const int2*   hash_table = (const int2*)d_in[1];
    const float*  W          = (const float*)d_in[2];
    const float2* P          = (const float2*)d_in[3];
    float*        out        = (float*)d_out;

    const int tokens_per_block = (256 / 32) * TPW;   // 32
    const int blocks = (NTOK + tokens_per_block - 1) / tokens_per_block;  // 25600
    hash_embedding_kernel<<<blocks, 256>>>(words, hash_table, W, P, out);
}

// round 4
// speedup vs baseline: 1.9235x; 1.1745x over previous
#include <cuda_runtime.h>
#include <cstdint>

// HashEmbedding: B*L=819200 tokens, H=2, E=64, out=[emb(64), pv0, pv1] f32
// d_in: words int32[819200], hash_table int32[1000000,2],
//       W f32[100000,64], P f32[1000000,2]

static constexpr int NTOK  = 16384 * 50;   // 819200
static constexpr int EMBED = 64;
static constexpr int OUTW  = EMBED + 2;    // 66
static constexpr int TPW   = 8;            // tokens per warp

__global__ void __launch_bounds__(256)
hash_embedding_kernel(const int*    __restrict__ words,
                      const int2*   __restrict__ hash_table,
                      const float*  __restrict__ W,
                      const float2* __restrict__ P2,
                      float*        __restrict__ out)
{
    const int warp = (blockIdx.x * blockDim.x + threadIdx.x) >> 5;
    const int lane = threadIdx.x & 31;
    const int base = warp * TPW;
    if (base >= NTOK) return;

    // Stage 1: 8 independent word loads (uniform addr -> 1 sector each, L1 bcast)
    int w[TPW];
#pragma unroll
    for (int t = 0; t < TPW; t++) w[t] = __ldg(&words[base + t]);

    // Stage 2: 16 independent gathers of hash indices + per-word weights
    int2   h[TPW];
    float2 pw[TPW];
#pragma unroll
    for (int t = 0; t < TPW; t++) h[t]  = __ldg(&hash_table[w[t]]);
#pragma unroll
    for (int t = 0; t < TPW; t++) pw[t] = __ldg(&P2[w[t]]);

    // Stage 3a: pvals distributed — lane t owns token t (every lane has all h[t]).
    // 2 gather instructions (8 lanes each) instead of 16 serial lane-0 loads.
    float2 pv;
    if (lane < TPW) {
        const float* Pf = reinterpret_cast<const float*>(P2);
        pv.x = __ldg(&Pf[(size_t)h[lane].x * 2 + 0]);
        pv.y = __ldg(&Pf[(size_t)h[lane].y * 2 + 1]);
    }

    // Stage 3b: 16 independent W-row gathers, 8B/lane, coalesced 256B rows.
    float2 a[TPW], b[TPW];
#pragma unroll
    for (int t = 0; t < TPW; t++) {
        a[t] = __ldg(reinterpret_cast<const float2*>(W + (size_t)h[t].x * EMBED) + lane);
        b[t] = __ldg(reinterpret_cast<const float2*>(W + (size_t)h[t].y * EMBED) + lane);
    }

    // Stage 4: consume in order (frees a[t]/b[t] registers early), store.
#pragma unroll
    for (int t = 0; t < TPW; t++) {
        float2 e;
        e.x = fmaf(a[t].x, pw[t].x, b[t].x * pw[t].y);
        e.y = fmaf(a[t].y, pw[t].x, b[t].y * pw[t].y);

        float* o = out + (size_t)(base + t) * OUTW;   // 264B stride, 8B aligned
        reinterpret_cast<float2*>(o)[lane] = e;       // cols 0..63
    }

    // pv store: 1 instruction, 8 active lanes (token (base+lane), cols 64..65)
    if (lane < TPW) {
        float* o = out + (size_t)(base + lane) * OUTW;
        *reinterpret_cast<float2*>(o + EMBED) = pv;
    }
}

extern "C" void kernel_launch(void* const* d_in, const int* in_sizes, int n_in,
                              void* d_out, int out_size)
{
    const int*    words      = (const int*)d_in[0];
    const int2*   hash_table = (const int2*)d_in[1];
    const float*  W          = (const float*)d_in[2];
    const float2* P          = (const float2*)d_in[3];
    float*        out        = (float*)d_out;

    const int tokens_per_block = (256 / 32) * TPW;   // 64
    const int blocks = (NTOK + tokens_per_block - 1) / tokens_per_block;  // 12800
    hash_embedding_kernel<<<blocks, 256>>>(words, hash_table, W, P, out);
}